// round 6
// baseline (speedup 1.0000x reference)
#include <cuda_runtime.h>
#include <math.h>

// Problem constants
#define B 64
#define S 4096
#define H 256
#define CHUNKS 16
#define ROWS_PER_CHUNK (S / CHUNKS)             // 256
#define WARPS 4
#define ROWS_PER_WARP (ROWS_PER_CHUNK / WARPS)  // 64
#define NEGC 1e30f

// Scratch: per (b, chunk): 256 acc + m + l (258 floats)
__device__ float g_scratch[B * CHUNKS * (H + 2)];
// Per-batch completion tickets (zero-init at load; last CTA resets each run)
__device__ int g_counters[B];

// ---------------------------------------------------------------------------
// Single fused kernel.
// grid = (CHUNKS, B) = 1024 CTAs, block = 128 (4 warps).
// Main loop: online-softmax partials with FULLY COALESCED loads:
//   lane owns elements {lane*4..+3, 128+lane*4..+3} -> each LDG.128 covers
//   512B contiguous (4 lines, 100% utilization) instead of 1024B strided.
// Tail: last CTA per batch (atomic ticket) combines the 16 chunk partials and
// computes the projection, overlapped with other batches' draining work.
// ---------------------------------------------------------------------------
__global__ void __launch_bounds__(128)
attn_fused_kernel(const float* __restrict__ inp,
                  const float* __restrict__ mask,
                  const float* __restrict__ query,
                  const float* __restrict__ W,
                  const float* __restrict__ bias,
                  float* __restrict__ out)
{
    const int chunk = blockIdx.x;
    const int b     = blockIdx.y;
    const int tid   = threadIdx.x;
    const int w     = tid >> 5;
    const int lane  = tid & 31;

    // lane's query slice: elements [lane*4, lane*4+4) and [128+lane*4, ...)
    float q[8];
    {
        const float4 q0 = *reinterpret_cast<const float4*>(query + (size_t)b * H + lane * 4);
        const float4 q1 = *reinterpret_cast<const float4*>(query + (size_t)b * H + 128 + lane * 4);
        q[0]=q0.x; q[1]=q0.y; q[2]=q0.z; q[3]=q0.w;
        q[4]=q1.x; q[5]=q1.y; q[6]=q1.z; q[7]=q1.w;
    }

    float m = -3.0e38f;
    float l = 0.0f;
    float acc[8];
    #pragma unroll
    for (int i = 0; i < 8; i++) acc[i] = 0.0f;

    const int s_base = chunk * ROWS_PER_CHUNK + w * ROWS_PER_WARP;
    const float* row  = inp  + ((size_t)b * S + s_base) * H + lane * 4;
    const float* mrow = mask + (size_t)b * S + s_base;

    for (int r = 0; r < ROWS_PER_WARP; r += 2) {
        // Row r: two coalesced 512B loads (first half / second half of H)
        const float4 a0 = *reinterpret_cast<const float4*>(row);
        const float4 a1 = *reinterpret_cast<const float4*>(row + 128);
        // Row r+1
        const float4 c0 = *reinterpret_cast<const float4*>(row + H);
        const float4 c1 = *reinterpret_cast<const float4*>(row + H + 128);
        const float mk0 = mrow[r];
        const float mk1 = mrow[r + 1];

        float d0 = q[0]*a0.x + q[1]*a0.y + q[2]*a0.z + q[3]*a0.w
                 + q[4]*a1.x + q[5]*a1.y + q[6]*a1.z + q[7]*a1.w;
        float d1 = q[0]*c0.x + q[1]*c0.y + q[2]*c0.z + q[3]*c0.w
                 + q[4]*c1.x + q[5]*c1.y + q[6]*c1.z + q[7]*c1.w;

        #pragma unroll
        for (int off = 16; off > 0; off >>= 1) {
            d0 += __shfl_xor_sync(0xffffffffu, d0, off);
            d1 += __shfl_xor_sync(0xffffffffu, d1, off);
        }

        const float sc0 = d0 - NEGC * (1.0f - mk0);
        const float sc1 = d1 - NEGC * (1.0f - mk1);
        const float mn  = fmaxf(m, fmaxf(sc0, sc1));
        const float alpha = __expf(m  - mn);
        const float p0    = __expf(sc0 - mn);
        const float p1    = __expf(sc1 - mn);
        l = l * alpha + p0 + p1;
        acc[0] = acc[0]*alpha + p0*a0.x + p1*c0.x;
        acc[1] = acc[1]*alpha + p0*a0.y + p1*c0.y;
        acc[2] = acc[2]*alpha + p0*a0.z + p1*c0.z;
        acc[3] = acc[3]*alpha + p0*a0.w + p1*c0.w;
        acc[4] = acc[4]*alpha + p0*a1.x + p1*c1.x;
        acc[5] = acc[5]*alpha + p0*a1.y + p1*c1.y;
        acc[6] = acc[6]*alpha + p0*a1.z + p1*c1.z;
        acc[7] = acc[7]*alpha + p0*a1.w + p1*c1.w;
        m = mn;
        row += 2 * H;
    }

    // ---- Block-level combine of 4 warp partials ----
    __shared__ float sm_m[WARPS];
    __shared__ float sm_l[WARPS];
    __shared__ float sm_acc[WARPS * H];
    __shared__ float conc[2 * H];
    __shared__ int   s_islast;

    if (lane == 0) { sm_m[w] = m; sm_l[w] = l; }
    #pragma unroll
    for (int i = 0; i < 4; i++) {
        sm_acc[w * H + lane * 4 + i]       = acc[i];
        sm_acc[w * H + 128 + lane * 4 + i] = acc[4 + i];
    }
    __syncthreads();

    float mb = sm_m[0];
    #pragma unroll
    for (int ww = 1; ww < WARPS; ww++) mb = fmaxf(mb, sm_m[ww]);

    float lb = 0.0f, ab0 = 0.0f, ab1 = 0.0f;
    #pragma unroll
    for (int ww = 0; ww < WARPS; ww++) {
        const float e = __expf(sm_m[ww] - mb);
        lb  += sm_l[ww] * e;
        ab0 += sm_acc[ww * H + tid] * e;
        ab1 += sm_acc[ww * H + tid + 128] * e;
    }

    float* dst = g_scratch + ((size_t)(b * CHUNKS + chunk)) * (H + 2);
    dst[tid]       = ab0;
    dst[tid + 128] = ab1;
    if (tid == 0) { dst[H] = mb; dst[H + 1] = lb; }

    // ---- Ticket: last CTA for this batch runs the tail ----
    __threadfence();
    if (tid == 0) {
        const int ticket = atomicAdd(&g_counters[b], 1);
        const int islast = (ticket == CHUNKS - 1);
        s_islast = islast;
        if (islast) g_counters[b] = 0;   // reset for next graph replay
    }
    __syncthreads();
    if (!s_islast) return;

    // ---- Tail phase A: combine the 16 chunk partials -> extracted_msg ----
    const float* base = g_scratch + (size_t)b * CHUNKS * (H + 2);

    float msv[CHUNKS];
    float mf = -3.0e38f;
    #pragma unroll
    for (int c = 0; c < CHUNKS; c++) {
        msv[c] = base[c * (H + 2) + H];
        mf = fmaxf(mf, msv[c]);
    }

    float lf = 0.0f, e0 = 0.0f, e1 = 0.0f;
    #pragma unroll
    for (int c = 0; c < CHUNKS; c++) {
        const float e = __expf(msv[c] - mf);
        lf += base[c * (H + 2) + H + 1] * e;
        e0 += base[c * (H + 2) + tid] * e;
        e1 += base[c * (H + 2) + tid + 128] * e;
    }

    const float inv = 1.0f / lf;
    const float ext0 = e0 * inv;
    const float ext1 = e1 * inv;
    out[(size_t)b * H + tid]       = ext0;
    out[(size_t)b * H + tid + 128] = ext1;

    conc[tid]             = query[(size_t)b * H + tid];
    conc[tid + 128]       = query[(size_t)b * H + tid + 128];
    conc[H + tid]         = ext0;
    conc[H + tid + 128]   = ext1;
    __syncthreads();

    // ---- Tail phase B: projection, warp-per-output (coalesced W reads) ----
    // Warp w covers j in [w*64, w*64+64), two outputs per iteration.
    float* outc = out + (size_t)B * H + (size_t)b * H;
    for (int jj = w * 64; jj < w * 64 + 64; jj += 2) {
        const int j0 = jj;
        const int j1 = jj + 1;
        const float4* w0p = reinterpret_cast<const float4*>(W + (size_t)j0 * (2 * H)) + lane;
        const float4* w1p = reinterpret_cast<const float4*>(W + (size_t)j1 * (2 * H)) + lane;

        float s0 = 0.0f, s1 = 0.0f;
        #pragma unroll
        for (int k = 0; k < 4; k++) {
            const float4 wv0 = w0p[k * 32];
            const float4 wv1 = w1p[k * 32];
            const float4 cv  = *reinterpret_cast<const float4*>(conc + (k * 32 + lane) * 4);
            s0 += wv0.x*cv.x + wv0.y*cv.y + wv0.z*cv.z + wv0.w*cv.w;
            s1 += wv1.x*cv.x + wv1.y*cv.y + wv1.z*cv.z + wv1.w*cv.w;
        }
        #pragma unroll
        for (int off = 16; off > 0; off >>= 1) {
            s0 += __shfl_xor_sync(0xffffffffu, s0, off);
            s1 += __shfl_xor_sync(0xffffffffu, s1, off);
        }
        if (lane == 0) {
            outc[j0] = s0 + bias[j0];
            outc[j1] = s1 + bias[j1];
        }
    }
}

// ---------------------------------------------------------------------------
// Launch: one kernel.
// ---------------------------------------------------------------------------
extern "C" void kernel_launch(void* const* d_in, const int* in_sizes, int n_in,
                              void* d_out, int out_size)
{
    const float* inp_seq = (const float*)d_in[0];  // [B,S,H]
    const float* mask    = (const float*)d_in[1];  // [B,S]
    const float* query   = (const float*)d_in[2];  // [B,H]
    const float* W       = (const float*)d_in[3];  // [H,2H]
    const float* bias    = (const float*)d_in[4];  // [H]
    float* out = (float*)d_out;                    // [B*H extracted | B*H control]

    dim3 grid(CHUNKS, B);
    attn_fused_kernel<<<grid, 128>>>(inp_seq, mask, query, W, bias, out);
}

// round 7
// speedup vs baseline: 1.2507x; 1.2507x over previous
#include <cuda_runtime.h>
#include <math.h>

// Problem constants
#define B 64
#define S 4096
#define H 256
#define CHUNKS 32
#define ROWS_PER_CHUNK (S / CHUNKS)             // 128
#define WARPS 4
#define ROWS_PER_WARP (ROWS_PER_CHUNK / WARPS)  // 32
#define NEGC 1e30f

// Scratch: per (b, chunk): 256 acc + m + l (258 floats) = 2.11 MB
__device__ float g_scratch[B * CHUNKS * (H + 2)];

// ---------------------------------------------------------------------------
// Kernel 1: streaming online-softmax partials.
// grid = (CHUNKS, B) = 2048 CTAs, block = 128, min 8 CTAs/SM -> 32 warps/SM.
// Coalesced mapping: lane owns elements {lane*4..+3, 128+lane*4..+3}; each
// LDG.128 covers 512B contiguous (4 lines/wavefronts vs 8 strided).
// ---------------------------------------------------------------------------
__global__ void __launch_bounds__(128, 8)
attn_partial_kernel(const float* __restrict__ inp,
                    const float* __restrict__ mask,
                    const float* __restrict__ query)
{
    const int chunk = blockIdx.x;
    const int b     = blockIdx.y;
    const int tid   = threadIdx.x;
    const int w     = tid >> 5;
    const int lane  = tid & 31;

    float q[8];
    {
        const float4 q0 = *reinterpret_cast<const float4*>(query + (size_t)b * H + lane * 4);
        const float4 q1 = *reinterpret_cast<const float4*>(query + (size_t)b * H + 128 + lane * 4);
        q[0]=q0.x; q[1]=q0.y; q[2]=q0.z; q[3]=q0.w;
        q[4]=q1.x; q[5]=q1.y; q[6]=q1.z; q[7]=q1.w;
    }

    float m = -3.0e38f;
    float l = 0.0f;
    float acc[8];
    #pragma unroll
    for (int i = 0; i < 8; i++) acc[i] = 0.0f;

    const int s_base = chunk * ROWS_PER_CHUNK + w * ROWS_PER_WARP;
    const float* row  = inp  + ((size_t)b * S + s_base) * H + lane * 4;
    const float* mrow = mask + (size_t)b * S + s_base;

    for (int r = 0; r < ROWS_PER_WARP; r += 2) {
        const float4 a0 = *reinterpret_cast<const float4*>(row);
        const float4 a1 = *reinterpret_cast<const float4*>(row + 128);
        const float4 c0 = *reinterpret_cast<const float4*>(row + H);
        const float4 c1 = *reinterpret_cast<const float4*>(row + H + 128);
        const float mk0 = mrow[r];
        const float mk1 = mrow[r + 1];

        float d0 = q[0]*a0.x + q[1]*a0.y + q[2]*a0.z + q[3]*a0.w
                 + q[4]*a1.x + q[5]*a1.y + q[6]*a1.z + q[7]*a1.w;
        float d1 = q[0]*c0.x + q[1]*c0.y + q[2]*c0.z + q[3]*c0.w
                 + q[4]*c1.x + q[5]*c1.y + q[6]*c1.z + q[7]*c1.w;

        #pragma unroll
        for (int off = 16; off > 0; off >>= 1) {
            d0 += __shfl_xor_sync(0xffffffffu, d0, off);
            d1 += __shfl_xor_sync(0xffffffffu, d1, off);
        }

        const float sc0 = d0 - NEGC * (1.0f - mk0);
        const float sc1 = d1 - NEGC * (1.0f - mk1);
        const float mn  = fmaxf(m, fmaxf(sc0, sc1));
        const float alpha = __expf(m  - mn);
        const float p0    = __expf(sc0 - mn);
        const float p1    = __expf(sc1 - mn);
        l = l * alpha + p0 + p1;
        acc[0] = acc[0]*alpha + p0*a0.x + p1*c0.x;
        acc[1] = acc[1]*alpha + p0*a0.y + p1*c0.y;
        acc[2] = acc[2]*alpha + p0*a0.z + p1*c0.z;
        acc[3] = acc[3]*alpha + p0*a0.w + p1*c0.w;
        acc[4] = acc[4]*alpha + p0*a1.x + p1*c1.x;
        acc[5] = acc[5]*alpha + p0*a1.y + p1*c1.y;
        acc[6] = acc[6]*alpha + p0*a1.z + p1*c1.z;
        acc[7] = acc[7]*alpha + p0*a1.w + p1*c1.w;
        m = mn;
        row += 2 * H;
    }

    // Block-level combine of 4 warp partials. Thread outputs h=tid, h=tid+128.
    __shared__ float sm_m[WARPS];
    __shared__ float sm_l[WARPS];
    __shared__ float sm_acc[WARPS * H];

    if (lane == 0) { sm_m[w] = m; sm_l[w] = l; }
    #pragma unroll
    for (int i = 0; i < 4; i++) {
        sm_acc[w * H + lane * 4 + i]       = acc[i];
        sm_acc[w * H + 128 + lane * 4 + i] = acc[4 + i];
    }
    __syncthreads();

    float mb = sm_m[0];
    #pragma unroll
    for (int ww = 1; ww < WARPS; ww++) mb = fmaxf(mb, sm_m[ww]);

    float lb = 0.0f, ab0 = 0.0f, ab1 = 0.0f;
    #pragma unroll
    for (int ww = 0; ww < WARPS; ww++) {
        const float e = __expf(sm_m[ww] - mb);
        lb  += sm_l[ww] * e;
        ab0 += sm_acc[ww * H + tid] * e;
        ab1 += sm_acc[ww * H + tid + 128] * e;
    }

    float* dst = g_scratch + ((size_t)(b * CHUNKS + chunk)) * (H + 2);
    dst[tid]       = ab0;
    dst[tid + 128] = ab1;
    if (tid == 0) { dst[H] = mb; dst[H + 1] = lb; }
}

// ---------------------------------------------------------------------------
// Kernel 2: fused combine + projection, warp-per-output.
// grid = (B, 16) = 1024 CTAs, block = 128 (4 warps).
// Phase A: every CTA combines the 32 chunk partials (redundant, L2-hot).
// Phase B: CTA (b, by) computes j in [by*16, by*16+16); each warp does 4 j's
// with coalesced W reads + shfl reduce. First pair's W prefetched before A.
// ---------------------------------------------------------------------------
__global__ void __launch_bounds__(128)
combine_proj_kernel(const float* __restrict__ query,
                    const float* __restrict__ W,
                    const float* __restrict__ bias,
                    float* __restrict__ out)
{
    const int b    = blockIdx.x;
    const int by   = blockIdx.y;
    const int t    = threadIdx.x;
    const int w    = t >> 5;
    const int lane = t & 31;

    __shared__ float conc[2 * H];

    const int j_base = by * 16 + w * 4;

    // Prefetch W rows for the first j-pair (overlaps latency-bound phase A)
    const float4* w0p = reinterpret_cast<const float4*>(W + (size_t)(j_base + 0) * (2 * H)) + lane;
    const float4* w1p = reinterpret_cast<const float4*>(W + (size_t)(j_base + 1) * (2 * H)) + lane;
    float4 w0r[4], w1r[4];
    #pragma unroll
    for (int k = 0; k < 4; k++) { w0r[k] = w0p[k * 32]; w1r[k] = w1p[k * 32]; }

    // --- Phase A: combine partials for h = t and h = t+128 ---
    const float* base = g_scratch + (size_t)b * CHUNKS * (H + 2);

    float m = -3.0e38f;
    float msv[CHUNKS];
    #pragma unroll
    for (int c = 0; c < CHUNKS; c++) {
        msv[c] = base[c * (H + 2) + H];
        m = fmaxf(m, msv[c]);
    }

    float l = 0.0f, a0 = 0.0f, a1 = 0.0f;
    #pragma unroll
    for (int c = 0; c < CHUNKS; c++) {
        const float e = __expf(msv[c] - m);
        l  += base[c * (H + 2) + H + 1] * e;
        a0 += base[c * (H + 2) + t] * e;
        a1 += base[c * (H + 2) + t + 128] * e;
    }

    const float inv  = 1.0f / l;
    const float ext0 = a0 * inv;
    const float ext1 = a1 * inv;
    if (by == 0) {
        out[(size_t)b * H + t]       = ext0;   // extracted_msg (once)
        out[(size_t)b * H + t + 128] = ext1;
    }
    conc[t]           = query[(size_t)b * H + t];
    conc[t + 128]     = query[(size_t)b * H + t + 128];
    conc[H + t]       = ext0;
    conc[H + t + 128] = ext1;
    __syncthreads();

    float* outc = out + (size_t)B * H + (size_t)b * H;

    // --- Phase B pair 0: from prefetched registers ---
    {
        float s0 = 0.0f, s1 = 0.0f;
        #pragma unroll
        for (int k = 0; k < 4; k++) {
            const float4 cv = *reinterpret_cast<const float4*>(conc + (k * 32 + lane) * 4);
            s0 += w0r[k].x*cv.x + w0r[k].y*cv.y + w0r[k].z*cv.z + w0r[k].w*cv.w;
            s1 += w1r[k].x*cv.x + w1r[k].y*cv.y + w1r[k].z*cv.z + w1r[k].w*cv.w;
        }
        #pragma unroll
        for (int off = 16; off > 0; off >>= 1) {
            s0 += __shfl_xor_sync(0xffffffffu, s0, off);
            s1 += __shfl_xor_sync(0xffffffffu, s1, off);
        }
        if (lane == 0) {
            outc[j_base + 0] = s0 + bias[j_base + 0];
            outc[j_base + 1] = s1 + bias[j_base + 1];
        }
    }
    // --- Phase B pair 1 ---
    {
        const int j0 = j_base + 2;
        const int j1 = j_base + 3;
        const float4* w2p = reinterpret_cast<const float4*>(W + (size_t)j0 * (2 * H)) + lane;
        const float4* w3p = reinterpret_cast<const float4*>(W + (size_t)j1 * (2 * H)) + lane;

        float s0 = 0.0f, s1 = 0.0f;
        #pragma unroll
        for (int k = 0; k < 4; k++) {
            const float4 wv0 = w2p[k * 32];
            const float4 wv1 = w3p[k * 32];
            const float4 cv  = *reinterpret_cast<const float4*>(conc + (k * 32 + lane) * 4);
            s0 += wv0.x*cv.x + wv0.y*cv.y + wv0.z*cv.z + wv0.w*cv.w;
            s1 += wv1.x*cv.x + wv1.y*cv.y + wv1.z*cv.z + wv1.w*cv.w;
        }
        #pragma unroll
        for (int off = 16; off > 0; off >>= 1) {
            s0 += __shfl_xor_sync(0xffffffffu, s0, off);
            s1 += __shfl_xor_sync(0xffffffffu, s1, off);
        }
        if (lane == 0) {
            outc[j0] = s0 + bias[j0];
            outc[j1] = s1 + bias[j1];
        }
    }
}

// ---------------------------------------------------------------------------
// Launch
// ---------------------------------------------------------------------------
extern "C" void kernel_launch(void* const* d_in, const int* in_sizes, int n_in,
                              void* d_out, int out_size)
{
    const float* inp_seq = (const float*)d_in[0];  // [B,S,H]
    const float* mask    = (const float*)d_in[1];  // [B,S]
    const float* query   = (const float*)d_in[2];  // [B,H]
    const float* W       = (const float*)d_in[3];  // [H,2H]
    const float* bias    = (const float*)d_in[4];  // [H]
    float* out = (float*)d_out;                    // [B*H extracted | B*H control]

    dim3 grid1(CHUNKS, B);
    attn_partial_kernel<<<grid1, 128>>>(inp_seq, mask, query);
    dim3 grid2(B, 16);
    combine_proj_kernel<<<grid2, 128>>>(query, W, bias, out);
}